// round 2
// baseline (speedup 1.0000x reference)
#include <cuda_runtime.h>
#include <cuda_bf16.h>

// NLL for mixed-model marginal likelihood with V = sig2e*I + sig2b*Z Z^T.
// V is block-diagonal per group (under permutation). Closed forms:
//   logdet V   = (N - G_nonempty)*log(sig2e) + sum_g log(sig2e + n_g*sig2b)
//   r^T V^-1 r = (1/sig2e) * [ sum_i r_i^2 - sum_g sig2b*s_g^2/(sig2e+n_g*sig2b) ]
// Single-block kernel: smem histogram + block reduction. O(N + G).
//
// R1 fix: Z_idx is int32 on device (JAX x64 disabled downcasts the declared
// int64), reading it as long long ran 2x past the buffer -> illegal access.

#define N_ELEMS 4096
#define NUM_GROUPS 1000
#define LOG_2PI 1.8378770664093453
#define NTHREADS 1024

__global__ __launch_bounds__(NTHREADS, 1)
void nll_closed_form_kernel(const float* __restrict__ y_true,
                            const float* __restrict__ y_pred,
                            const int*   __restrict__ z_idx,
                            const float* __restrict__ p_sig2e,
                            const float* __restrict__ p_sig2b,
                            float* __restrict__ out)
{
    __shared__ float  s_sum[NUM_GROUPS];
    __shared__ int    s_cnt[NUM_GROUPS];
    __shared__ double s_red[3][32];   // block-reduce scratch: [ss, logdet, quad]

    const int tid = threadIdx.x;

    // zero histogram
    for (int g = tid; g < NUM_GROUPS; g += NTHREADS) {
        s_sum[g] = 0.0f;
        s_cnt[g] = 0;
    }
    __syncthreads();

    // residual pass: sum of squares + per-group (count, sum)
    float ss_local = 0.0f;
    #pragma unroll
    for (int i = tid; i < N_ELEMS; i += NTHREADS) {
        float r = y_true[i] - y_pred[i];
        ss_local += r * r;
        int g = z_idx[i];
        // defensive clamp: never trap on smem even if dtype surprises us
        g = (g < 0) ? 0 : (g >= NUM_GROUPS ? NUM_GROUPS - 1 : g);
        atomicAdd(&s_sum[g], r);
        atomicAdd(&s_cnt[g], 1);
    }
    __syncthreads();

    const float sig2e = *p_sig2e;
    const float sig2b = *p_sig2b;
    const float log_sig2e = logf(sig2e);

    // per-group closed-form terms
    double logdet_local = 0.0;
    double quad_local   = 0.0;
    for (int g = tid; g < NUM_GROUPS; g += NTHREADS) {
        int n = s_cnt[g];
        if (n > 0) {
            float d = sig2e + (float)n * sig2b;
            logdet_local += (double)(logf(d) - log_sig2e);
            float s = s_sum[g];
            quad_local += (double)(sig2b * s * s / d);
        }
    }

    // block reduction of three scalars (warp shuffle + smem)
    double v0 = (double)ss_local, v1 = logdet_local, v2 = quad_local;
    unsigned mask = 0xFFFFFFFFu;
    #pragma unroll
    for (int off = 16; off > 0; off >>= 1) {
        v0 += __shfl_down_sync(mask, v0, off);
        v1 += __shfl_down_sync(mask, v1, off);
        v2 += __shfl_down_sync(mask, v2, off);
    }
    int lane = tid & 31;
    int wid  = tid >> 5;
    if (lane == 0) {
        s_red[0][wid] = v0;
        s_red[1][wid] = v1;
        s_red[2][wid] = v2;
    }
    __syncthreads();
    if (wid == 0) {
        v0 = s_red[0][lane];
        v1 = s_red[1][lane];
        v2 = s_red[2][lane];
        #pragma unroll
        for (int off = 16; off > 0; off >>= 1) {
            v0 += __shfl_down_sync(mask, v0, off);
            v1 += __shfl_down_sync(mask, v1, off);
            v2 += __shfl_down_sync(mask, v2, off);
        }
        if (lane == 0) {
            double logdet = (double)N_ELEMS * (double)log_sig2e + v1;
            double quad   = (v0 - v2) / (double)sig2e;
            double total  = 0.5 * (double)N_ELEMS * LOG_2PI
                          + 0.5 * logdet
                          + 0.5 * quad;
            out[0] = (float)total;
        }
    }
}

extern "C" void kernel_launch(void* const* d_in, const int* in_sizes, int n_in,
                              void* d_out, int out_size)
{
    const float* y_true = (const float*)d_in[0];
    const float* y_pred = (const float*)d_in[1];
    const int*   z_idx  = (const int*)d_in[2];
    const float* sig2e  = (const float*)d_in[3];
    const float* sig2b  = (const float*)d_in[4];
    float*       out    = (float*)d_out;

    nll_closed_form_kernel<<<1, NTHREADS>>>(y_true, y_pred, z_idx, sig2e, sig2b, out);
}

// round 4
// speedup vs baseline: 1.2196x; 1.2196x over previous
#include <cuda_runtime.h>
#include <cuda_bf16.h>

// NLL closed form for V = sig2e*I + sig2b*Z Z^T (block-diagonal per group):
//   logdet V   = N*log(sig2e) + sum_{g nonempty} [log(sig2e + n_g*sig2b) - log(sig2e)]
//   r^T V^-1 r = (1/sig2e) * [ sum r_i^2 - sum_g sig2b*s_g^2/(sig2e+n_g*sig2b) ]
//
// Multi-CTA pass fires ONE packed 64-bit REDG per element into an L2-resident
// histogram; kernel2 decodes, finishes the math, re-zeroes scratch.
//
// R3 fix: the old (v & MASK) packing carried +1 into the count field for every
// NEGATIVE residual. Now each element adds BIAS=2^32 to the fixed-point value
// (always positive), sum lives in bits [0:46), count in bits [46:64).
// Group sum < 4096*(2^32+2^30) < 2^45 -> no carry. Decode subtracts n*BIAS.

#define N_ELEMS    4096
#define NUM_GROUPS 1000
#define LOG_2PI    1.8378770664093453
#define K1_CTAS    8
#define K1_THREADS 512
#define K2_THREADS 1024

#define FX_SCALE   67108864.0f            // 2^26
#define FX_INV_D   (1.0 / 67108864.0)
#define SUM_BITS   46
#define MASK46     ((1ULL << SUM_BITS) - 1ULL)
#define CNT_ONE    (1ULL << SUM_BITS)
#define BIAS       (1LL << 32)

// Persistent scratch (zero at module load; kernel2 re-zeroes after consuming).
__device__ unsigned long long g_hist[NUM_GROUPS];
__device__ unsigned long long g_ss_fx;

__global__ __launch_bounds__(K1_THREADS, 1)
void nll_hist_kernel(const float* __restrict__ y_true,
                     const float* __restrict__ y_pred,
                     const int*   __restrict__ z_idx)
{
    const int i = blockIdx.x * K1_THREADS + threadIdx.x;

    float r = y_true[i] - y_pred[i];
    int   g = z_idx[i];
    g = (g < 0) ? 0 : (g >= NUM_GROUPS ? NUM_GROUPS - 1 : g);

    // biased fixed-point: u = round(r*2^26) + 2^32  (always in (0, 2^33))
    long long u = llrintf(r * FX_SCALE) + BIAS;
    unsigned long long packed = CNT_ONE + (unsigned long long)u;
    atomicAdd(&g_hist[g], packed);

    // sum of squares: warp-reduce, one integer RED per warp (deterministic).
    float ss = r * r;
    #pragma unroll
    for (int off = 16; off > 0; off >>= 1)
        ss += __shfl_down_sync(0xFFFFFFFFu, ss, off);
    if ((threadIdx.x & 31) == 0) {
        unsigned long long ss_fx = (unsigned long long)llrintf(ss * FX_SCALE);
        atomicAdd(&g_ss_fx, ss_fx);
    }
}

__global__ __launch_bounds__(K2_THREADS, 1)
void nll_finish_kernel(const float* __restrict__ p_sig2e,
                       const float* __restrict__ p_sig2b,
                       float* __restrict__ out)
{
    __shared__ double s_red[2][32];

    const int tid  = threadIdx.x;
    const int lane = tid & 31;
    const int wid  = tid >> 5;

    const float sig2e = *p_sig2e;
    const float sig2b = *p_sig2b;
    const float log_sig2e = logf(sig2e);

    float logdet_adj = 0.0f;   // sum_g [log(sig2e + n_g sig2b) - log(sig2e)]
    float quad_sub   = 0.0f;   // sum_g sig2b * s_g^2 / (sig2e + n_g sig2b)

    if (tid < NUM_GROUPS) {
        unsigned long long h = g_hist[tid];
        g_hist[tid] = 0ULL;                        // restore for next replay
        int       n    = (int)(h >> SUM_BITS);
        long long s_fx = (long long)(h & MASK46) - (long long)n * BIAS;
        if (n > 0) {
            float d = sig2e + (float)n * sig2b;
            float s = (float)((double)s_fx * FX_INV_D);
            logdet_adj = logf(d) - log_sig2e;
            quad_sub   = sig2b * s * s / d;
        }
    }

    // block reduce two scalars (deterministic shuffle tree)
    double v1 = (double)logdet_adj, v2 = (double)quad_sub;
    #pragma unroll
    for (int off = 16; off > 0; off >>= 1) {
        v1 += __shfl_down_sync(0xFFFFFFFFu, v1, off);
        v2 += __shfl_down_sync(0xFFFFFFFFu, v2, off);
    }
    if (lane == 0) { s_red[0][wid] = v1; s_red[1][wid] = v2; }
    __syncthreads();
    if (wid == 0) {
        v1 = s_red[0][lane];
        v2 = s_red[1][lane];
        #pragma unroll
        for (int off = 16; off > 0; off >>= 1) {
            v1 += __shfl_down_sync(0xFFFFFFFFu, v1, off);
            v2 += __shfl_down_sync(0xFFFFFFFFu, v2, off);
        }
        if (lane == 0) {
            unsigned long long ssfx = g_ss_fx;
            g_ss_fx = 0ULL;                        // restore for next replay
            double ss = (double)ssfx * FX_INV_D;

            double logdet = (double)N_ELEMS * (double)log_sig2e + v1;
            double quad   = (ss - v2) / (double)sig2e;
            double total  = 0.5 * (double)N_ELEMS * LOG_2PI
                          + 0.5 * logdet
                          + 0.5 * quad;
            out[0] = (float)total;
        }
    }
}

extern "C" void kernel_launch(void* const* d_in, const int* in_sizes, int n_in,
                              void* d_out, int out_size)
{
    const float* y_true = (const float*)d_in[0];
    const float* y_pred = (const float*)d_in[1];
    const int*   z_idx  = (const int*)d_in[2];
    const float* sig2e  = (const float*)d_in[3];
    const float* sig2b  = (const float*)d_in[4];
    float*       out    = (float*)d_out;

    nll_hist_kernel<<<K1_CTAS, K1_THREADS>>>(y_true, y_pred, z_idx);
    nll_finish_kernel<<<1, K2_THREADS>>>(sig2e, sig2b, out);
}

// round 5
// speedup vs baseline: 1.7353x; 1.4228x over previous
#include <cuda_runtime.h>
#include <cuda_bf16.h>

// NLL closed form for V = sig2e*I + sig2b*Z Z^T (block-diagonal per group):
//   logdet V   = N*log(sig2e) + sum_{g:n_g>0} [log(sig2e + n_g*sig2b) - log(sig2e)]
//   r^T V^-1 r = (1/sig2e) * [ sum r_i^2 - sum_g sig2b*s_g^2/(sig2e+n_g*sig2b) ]
//
// Fused single kernel (R5): 8 CTAs fire one packed 64-bit REDG per element
// into an L2-resident histogram (count in bits[46:64), biased fixed-point sum
// in bits[0:46): u = round(r*2^26)+2^32 is always positive, group sum < 2^45,
// no carry into count). Each CTA then fences and takes a ticket; the LAST CTA
// needs no spin (all earlier CTAs' fenced atomics are visible) and finishes:
// decode 1000 bins with 512 threads, float shuffle-tree reduce, write out,
// re-zero all scratch for the next graph replay.

#define N_ELEMS    4096
#define NUM_GROUPS 1000
#define LOG_2PI    1.8378770664093453
#define NCTAS      8
#define NTHREADS   512

#define FX_SCALE   67108864.0f            // 2^26
#define FX_INV_D   (1.0 / 67108864.0)
#define SUM_BITS   46
#define MASK46     ((1ULL << SUM_BITS) - 1ULL)
#define CNT_ONE    (1ULL << SUM_BITS)
#define BIAS       (1LL << 32)

// Persistent scratch (zero at module load; finisher re-zeroes each launch).
__device__ unsigned long long g_hist[NUM_GROUPS];
__device__ unsigned long long g_ss_fx;
__device__ unsigned int       g_done;

__global__ __launch_bounds__(NTHREADS, 1)
void nll_fused_kernel(const float* __restrict__ y_true,
                      const float* __restrict__ y_pred,
                      const int*   __restrict__ z_idx,
                      const float* __restrict__ p_sig2e,
                      const float* __restrict__ p_sig2b,
                      float* __restrict__ out)
{
    __shared__ float s_red[2][16];
    __shared__ int   s_last;

    const int tid  = threadIdx.x;
    const int lane = tid & 31;
    const int wid  = tid >> 5;
    const int i    = blockIdx.x * NTHREADS + tid;

    // ---- element pass: one packed REDG per element ----
    float r = y_true[i] - y_pred[i];
    int   g = z_idx[i];
    g = (g < 0) ? 0 : (g >= NUM_GROUPS ? NUM_GROUPS - 1 : g);

    long long u = llrintf(r * FX_SCALE) + BIAS;     // in (0, 2^33)
    atomicAdd(&g_hist[g], CNT_ONE + (unsigned long long)u);

    // sum of squares: warp shuffle + one integer RED per warp (deterministic)
    float ss = r * r;
    #pragma unroll
    for (int off = 16; off > 0; off >>= 1)
        ss += __shfl_down_sync(0xFFFFFFFFu, ss, off);
    if (lane == 0)
        atomicAdd(&g_ss_fx, (unsigned long long)llrintf(ss * FX_SCALE));

    // ---- release our atomics, take a ticket; last CTA finishes ----
    __threadfence();
    __syncthreads();
    if (tid == 0) {
        unsigned t = atomicAdd(&g_done, 1u);
        s_last = (t == NCTAS - 1);
        __threadfence();                            // acquire side
    }
    __syncthreads();
    if (!s_last) return;

    // ---- finish (last CTA only): decode bins, closed-form terms ----
    const float sig2e = *p_sig2e;
    const float sig2b = *p_sig2b;
    const float log_sig2e = __logf(sig2e);

    float v1 = 0.0f;   // sum_g [log(sig2e + n_g sig2b) - log(sig2e)]
    float v2 = 0.0f;   // sum_g sig2b * s_g^2 / (sig2e + n_g sig2b)

    #pragma unroll
    for (int k = 0; k < 2; k++) {
        int gg = tid + k * NTHREADS;
        if (gg < NUM_GROUPS) {
            unsigned long long h = g_hist[gg];
            g_hist[gg] = 0ULL;                      // restore for next replay
            int       n    = (int)(h >> SUM_BITS);
            long long s_fx = (long long)(h & MASK46) - (long long)n * BIAS;
            if (n > 0) {
                float d = sig2e + (float)n * sig2b;
                float s = (float)((double)s_fx * FX_INV_D);
                v1 += __logf(d) - log_sig2e;
                v2 += __fdividef(sig2b * s * s, d);
            }
        }
    }

    // float block reduction: 16 warps -> smem -> warp 0
    #pragma unroll
    for (int off = 16; off > 0; off >>= 1) {
        v1 += __shfl_down_sync(0xFFFFFFFFu, v1, off);
        v2 += __shfl_down_sync(0xFFFFFFFFu, v2, off);
    }
    if (lane == 0) { s_red[0][wid] = v1; s_red[1][wid] = v2; }
    __syncthreads();
    if (wid == 0) {
        v1 = (lane < 16) ? s_red[0][lane] : 0.0f;
        v2 = (lane < 16) ? s_red[1][lane] : 0.0f;
        #pragma unroll
        for (int off = 8; off > 0; off >>= 1) {
            v1 += __shfl_down_sync(0xFFFFFFFFu, v1, off);
            v2 += __shfl_down_sync(0xFFFFFFFFu, v2, off);
        }
        if (lane == 0) {
            unsigned long long ssfx = g_ss_fx;
            g_ss_fx = 0ULL;                         // restore for next replay
            g_done  = 0u;
            double ss = (double)ssfx * FX_INV_D;

            double logdet = (double)N_ELEMS * (double)log_sig2e + (double)v1;
            double quad   = (ss - (double)v2) / (double)sig2e;
            double total  = 0.5 * (double)N_ELEMS * LOG_2PI
                          + 0.5 * logdet
                          + 0.5 * quad;
            out[0] = (float)total;
        }
    }
}

extern "C" void kernel_launch(void* const* d_in, const int* in_sizes, int n_in,
                              void* d_out, int out_size)
{
    const float* y_true = (const float*)d_in[0];
    const float* y_pred = (const float*)d_in[1];
    const int*   z_idx  = (const int*)d_in[2];
    const float* sig2e  = (const float*)d_in[3];
    const float* sig2b  = (const float*)d_in[4];
    float*       out    = (float*)d_out;

    nll_fused_kernel<<<NCTAS, NTHREADS>>>(y_true, y_pred, z_idx, sig2e, sig2b, out);
}